// round 16
// baseline (speedup 1.0000x reference)
#include <cuda_runtime.h>
#include <cuda_fp16.h>
#include <cstdint>

#define N_MOLS        2000
#define ATOMS_PER_MOL 50
#define N_ATOMS       (N_MOLS * ATOMS_PER_MOL + 1)   // 100001
#define N_BONDS       200001
#define MAX_NB        6
#define ATOM_FDIM     133
#define BOND_FDIM     147
#define HIDDEN        300
#define DEPTH         4
#define H4            (HIDDEN / 4)
#define FBH           152                    // f_bonds halves padded (304B rows)
#define MSGH          304                    // msg/amsg/inp row stride in halves (608B)
#define CATH          440                    // cat K padded halves (880B rows)

// ---------------- persistent scratch (zero-initialized; pads stay 0) ----------------
__device__ __align__(16) float  g_ah   [(size_t)N_ATOMS * HIDDEN];  // fp32 (precision anchor)
__device__ __align__(16) __half g_inpH [(size_t)N_BONDS * MSGH];    // fp16 pre-relu W_i output
__device__ __align__(16) __half g_msgA [(size_t)N_BONDS * MSGH];    // fp16 message (ping)
__device__ __align__(16) __half g_msgB [(size_t)N_BONDS * MSGH];    // fp16 message (pong)
__device__ __align__(16) __half g_amsgH[(size_t)N_ATOMS * MSGH];    // fp16 atom aggregate
__device__ __align__(16) __half g_fbtH [(size_t)N_BONDS * FBH];     // fp16 f_bonds, padded
__device__ __align__(16) __half g_catH [(size_t)N_ATOMS * CATH];    // fp16 [amsg | f_atoms | 0]
__device__ __align__(16) __half g_WiT  [HIDDEN * 160];              // W_i^T  [300][160]
__device__ __align__(16) __half g_WhT  [HIDDEN * MSGH];             // W_h^T  [300][304]
__device__ __align__(16) __half g_WoT  [HIDDEN * CATH];             // WoC^T  [300][440]

// ---------------- pre-conversion kernels ----------------
__global__ void cvt_padH(const float* __restrict__ in, __half* __restrict__ out,
                         int n, int cin, int coutH) {
    int i = blockIdx.x * blockDim.x + threadIdx.x;
    if (i >= n) return;
    int r = i / coutH, c = i - r * coutH;
    out[i] = (c < cin) ? __float2half_rn(in[(size_t)r * cin + c]) : __half(0.f);
}
__global__ void cvt_wtrH(const float* __restrict__ W, __half* __restrict__ Bt,
                         int K, int kpad, int n) {   // n = 300*kpad
    int i = blockIdx.x * blockDim.x + threadIdx.x;
    if (i >= n) return;
    int nn = i / kpad, k = i - nn * kpad;
    Bt[i] = (k < K) ? __float2half_rn(W[(size_t)k * HIDDEN + nn]) : __half(0.f);
}
__global__ void cvt_wo_trH(const float* __restrict__ Wo, __half* __restrict__ Bt, int n) {
    int i = blockIdx.x * blockDim.x + threadIdx.x;   // n = 300*CATH
    if (i >= n) return;
    int nn = i / CATH, kp = i - nn * CATH;
    float v = 0.f;
    if (kp < HIDDEN)                  v = Wo[(size_t)(ATOM_FDIM + kp) * HIDDEN + nn];
    else if (kp < HIDDEN + ATOM_FDIM) v = Wo[(size_t)(kp - HIDDEN) * HIDDEN + nn];
    Bt[i] = __float2half_rn(v);
}
__global__ void cvt_cat_atomsH(const float* __restrict__ fa, __half* __restrict__ cat, int n) {
    int i = blockIdx.x * blockDim.x + threadIdx.x;   // n = N_ATOMS * 140
    if (i >= n) return;
    int r = i / 140, c = i - r * 140;
    cat[(size_t)r * CATH + HIDDEN + c] =
        (c < ATOM_FDIM) ? __float2half_rn(fa[(size_t)r * ATOM_FDIM + c]) : __half(0.f);
}

// ---------------- fp16 mma ----------------
__device__ __forceinline__ void mma_f16(float* c, const uint32_t* a, const uint32_t* b) {
    asm volatile(
        "mma.sync.aligned.m16n8k16.row.col.f32.f16.f16.f32 "
        "{%0,%1,%2,%3}, {%4,%5,%6,%7}, {%8,%9}, {%0,%1,%2,%3};"
        : "+f"(c[0]), "+f"(c[1]), "+f"(c[2]), "+f"(c[3])
        : "r"(a[0]), "r"(a[1]), "r"(a[2]), "r"(a[3]), "r"(b[0]), "r"(b[1]));
}
__device__ __forceinline__ uint32_t hfma2u(uint32_t m, uint32_t w, uint32_t a) {
    uint32_t r;
    asm("fma.rn.f16x2 %0, %1, %2, %3;" : "=r"(r) : "r"(m), "r"(w), "r"(a));
    return r;
}

// ---------------- pipelined fp16 tensor-core GEMM, 64x40 warp tiles, TBK=32 ----------------
// FUSED=0: A[M,K] streamed from memory.
// FUSED=1: A row b = amsgH[b2a[b]] - w_bonds[b] * msgSrc[b2revb[b]], formed from two
//          cp.async-gathered smem regions at fragment-load time (HFMA2). K = MSGH.
//          msgSrc is NEVER the output buffer (caller ping-pongs).
#define TBM 128
#define TBN 160
#define STAGES 3
#define RST 20
#define A_WORDS (TBM * RST)            // 2560
#define B_WORDS (TBN * RST)            // 3200
#define SMEM_PLAIN (STAGES * (A_WORDS + B_WORDS) * 4)       // 69120
#define SMEM_FUSED (STAGES * (2 * A_WORDS + B_WORDS) * 4)   // 99840

template <int FUSED>
__global__ __launch_bounds__(256, 2) void hgemm300(
    const __half* __restrict__ A, int ldaH,
    const __half* __restrict__ Bt, int ldbH,
    __half* __restrict__ Ch, int ldcH,
    float* __restrict__ Cf,
    const __half* __restrict__ addsrcH, int ldaddH,
    const float* __restrict__ bias,
    __half* __restrict__ rawoutH, int ldrawH,
    int M, int nCh, int doRelu,
    const __half* __restrict__ amsgH, const __half* __restrict__ msgSrc,
    const int* __restrict__ b2a, const int* __restrict__ b2revb,
    const float* __restrict__ wB)
{
    extern __shared__ uint32_t sm[];
    constexpr int A_REGION = A_WORDS * (FUSED ? 2 : 1);
    uint32_t* sA = sm;
    uint32_t* sB = sm + STAGES * A_REGION;
    const uint32_t sAaddr = (uint32_t)__cvta_generic_to_shared(sA);
    const uint32_t sBaddr = (uint32_t)__cvta_generic_to_shared(sB);

    __shared__ int      sIA[TBM], sIR[TBM];
    __shared__ uint32_t sWn[TBM];          // half2(-w,-w)

    const int tid  = threadIdx.x;
    const int lane = tid & 31;
    const int warp = tid >> 5;
    const int g = lane >> 2;
    const int t = lane & 3;
    const int m0w = (warp & 1) * 64;
    const int n0w = (warp >> 1) * 40;

    const int rowBase = blockIdx.y * TBM;
    const int colBase = blockIdx.x * TBN;

    if (FUSED) {
        if (tid < TBM) {
            int gr = rowBase + tid;
            int ia = 0, ir = 0; float w = 0.f;
            if (gr < M) { ia = b2a[gr]; ir = b2revb[gr]; w = wB[gr]; }
            sIA[tid] = ia; sIR[tid] = ir;
            __half2 h = __float2half2_rn(-w);
            sWn[tid] = *reinterpret_cast<uint32_t*>(&h);
        }
        __syncthreads();
    }

    auto issue = [&](int c) {
        const int stg = c % STAGES;
        if (FUSED) {
            // amsg part [0,512) + msg part [512,1024): 16B chunks
            #pragma unroll
            for (int it = 0; it < 4; it++) {
                int e    = it * 256 + tid;
                int part = e >> 9;
                int e2   = e & 511;
                int row  = e2 >> 2;
                int k16  = e2 & 3;
                int gr   = rowBase + row;
                int k0h  = c * 32 + k16 * 8;
                int by   = (gr < M && k0h < MSGH) ? 16 : 0;
                const __half* base = part ? msgSrc : amsgH;
                int idx = part ? sIR[row] : sIA[row];
                const __half* src = by ? (base + (size_t)idx * MSGH + k0h) : base;
                uint32_t dst = sAaddr +
                    (uint32_t)(stg * A_REGION + part * A_WORDS + row * RST + k16 * 4) * 4u;
                asm volatile("cp.async.ca.shared.global [%0], [%1], 16, %2;"
                             :: "r"(dst), "l"(src), "r"(by) : "memory");
            }
        } else {
            #pragma unroll
            for (int it = 0; it < 2; it++) {
                int e   = it * 256 + tid;
                int row = e >> 2;
                int k16 = e & 3;
                int gr  = rowBase + row;
                int k0h = c * 32 + k16 * 8;
                int by  = (gr < M && k0h < ldaH) ? 16 : 0;
                const __half* src = by ? (A + (size_t)gr * ldaH + k0h) : A;
                uint32_t dst = sAaddr + (uint32_t)(stg * A_REGION + row * RST + k16 * 4) * 4u;
                asm volatile("cp.async.ca.shared.global [%0], [%1], 16, %2;"
                             :: "r"(dst), "l"(src), "r"(by) : "memory");
            }
        }
        #pragma unroll
        for (int it = 0; it < 3; it++) {
            int e = it * 256 + tid;
            if (it == 2 && tid >= 128) break;
            int n   = e >> 2;
            int k16 = e & 3;
            int gn  = colBase + n;
            int k0h = c * 32 + k16 * 8;
            int by  = (gn < HIDDEN && k0h < ldbH) ? 16 : 0;
            const __half* src = by ? (Bt + (size_t)gn * ldbH + k0h) : Bt;
            uint32_t dst = sBaddr + (uint32_t)(stg * B_WORDS + n * RST + k16 * 4) * 4u;
            asm volatile("cp.async.ca.shared.global [%0], [%1], 16, %2;"
                         :: "r"(dst), "l"(src), "r"(by) : "memory");
        }
    };

    // per-thread -w half2 for each mt (fused)
    uint32_t wlo[4], whi[4];
    if (FUSED) {
        #pragma unroll
        for (int mt = 0; mt < 4; mt++) {
            wlo[mt] = sWn[m0w + mt * 16 + g];
            whi[mt] = sWn[m0w + mt * 16 + g + 8];
        }
    }

    float acc[4][5][4];
    #pragma unroll
    for (int i = 0; i < 4; i++)
        #pragma unroll
        for (int j = 0; j < 5; j++)
            #pragma unroll
            for (int q = 0; q < 4; q++) acc[i][j][q] = 0.f;

    #pragma unroll
    for (int s = 0; s < STAGES - 1; s++) {
        if (s < nCh) issue(s);
        asm volatile("cp.async.commit_group;" ::: "memory");
    }

    for (int c = 0; c < nCh; c++) {
        asm volatile("cp.async.wait_group %0;" :: "n"(STAGES - 2) : "memory");
        __syncthreads();
        const uint32_t* As  = sA + (c % STAGES) * A_REGION;
        const uint32_t* AsM = As + A_WORDS;       // msg part (fused only)
        const uint32_t* Bs  = sB + (c % STAGES) * B_WORDS;

        #pragma unroll
        for (int ks = 0; ks < 2; ks++) {
            const int kkw = ks * 8;
            uint32_t af[4][4];
            #pragma unroll
            for (int mt = 0; mt < 4; mt++) {
                int r = m0w + mt * 16;
                uint32_t a0 = As[(r + g    ) * RST + kkw + t    ];
                uint32_t a1 = As[(r + g + 8) * RST + kkw + t    ];
                uint32_t a2 = As[(r + g    ) * RST + kkw + t + 4];
                uint32_t a3 = As[(r + g + 8) * RST + kkw + t + 4];
                if (FUSED) {
                    uint32_t m0 = AsM[(r + g    ) * RST + kkw + t    ];
                    uint32_t m1 = AsM[(r + g + 8) * RST + kkw + t    ];
                    uint32_t m2 = AsM[(r + g    ) * RST + kkw + t + 4];
                    uint32_t m3 = AsM[(r + g + 8) * RST + kkw + t + 4];
                    af[mt][0] = hfma2u(m0, wlo[mt], a0);
                    af[mt][1] = hfma2u(m1, whi[mt], a1);
                    af[mt][2] = hfma2u(m2, wlo[mt], a2);
                    af[mt][3] = hfma2u(m3, whi[mt], a3);
                } else {
                    af[mt][0] = a0; af[mt][1] = a1; af[mt][2] = a2; af[mt][3] = a3;
                }
            }
            uint32_t bf[5][2];
            #pragma unroll
            for (int nt = 0; nt < 5; nt++) {
                int nc = n0w + nt * 8 + g;
                bf[nt][0] = Bs[nc * RST + kkw + t    ];
                bf[nt][1] = Bs[nc * RST + kkw + t + 4];
            }
            #pragma unroll
            for (int mt = 0; mt < 4; mt++)
                #pragma unroll
                for (int nt = 0; nt < 5; nt++)
                    mma_f16(acc[mt][nt], af[mt], bf[nt]);
        }
        int nx = c + STAGES - 1;
        if (nx < nCh) issue(nx);
        asm volatile("cp.async.commit_group;" ::: "memory");
    }

    // epilogue (col pairs are even and never straddle the N=300 edge)
    #pragma unroll
    for (int mt = 0; mt < 4; mt++) {
        #pragma unroll
        for (int half = 0; half < 2; half++) {
            int row = rowBase + m0w + mt * 16 + g + half * 8;
            if (row >= M) continue;
            #pragma unroll
            for (int nt = 0; nt < 5; nt++) {
                int col = colBase + n0w + nt * 8 + t * 2;
                if (col >= HIDDEN) continue;
                float vx = acc[mt][nt][half * 2 + 0];
                float vy = acc[mt][nt][half * 2 + 1];
                if (bias)   { vx += bias[col]; vy += bias[col + 1]; }
                if (addsrcH) {
                    float2 a = __half22float2(
                        *reinterpret_cast<const __half2*>(addsrcH + (size_t)row * ldaddH + col));
                    vx += a.x; vy += a.y;
                }
                if (rawoutH) {
                    *reinterpret_cast<__half2*>(rawoutH + (size_t)row * ldrawH + col) =
                        __floats2half2_rn(vx, vy);
                }
                if (doRelu) { vx = fmaxf(vx, 0.f); vy = fmaxf(vy, 0.f); }
                if (Ch) {
                    *reinterpret_cast<__half2*>(Ch + (size_t)row * ldcH + col) =
                        __floats2half2_rn(vx, vy);
                } else {
                    float2 o; o.x = vx; o.y = vy;
                    *reinterpret_cast<float2*>(Cf + (size_t)row * HIDDEN + col) = o;
                }
            }
        }
    }
}

// ---------------- atom aggregation: fp16 msg in -> fp16 out (amsg or cat) ----------------
__global__ __launch_bounds__(320) void gather_atomsH(
    const __half* __restrict__ msgH, const float* __restrict__ w_bonds,
    const int* __restrict__ a2b, __half* __restrict__ outH, int outStrideH)
{
    const int tx = threadIdx.x;        // 0..79
    const int ty = threadIdx.y;        // 0..3
    const int a  = blockIdx.x * 4 + ty;
    __shared__ int   sb[4][MAX_NB];
    __shared__ float sw[4][MAX_NB];
    if (a < N_ATOMS && tx < MAX_NB) {
        int b = a2b[(size_t)a * MAX_NB + tx];
        sb[ty][tx] = b;
        sw[ty][tx] = w_bonds[b];
    }
    __syncthreads();
    if (a < N_ATOMS && tx < H4) {
        float4 acc = make_float4(0.f, 0.f, 0.f, 0.f);
        #pragma unroll
        for (int k = 0; k < MAX_NB; k++) {
            float w = sw[ty][k];
            const __half2* p = reinterpret_cast<const __half2*>(
                msgH + (size_t)sb[ty][k] * MSGH + tx * 4);
            float2 v0 = __half22float2(p[0]);
            float2 v1 = __half22float2(p[1]);
            acc.x = fmaf(w, v0.x, acc.x);
            acc.y = fmaf(w, v0.y, acc.y);
            acc.z = fmaf(w, v1.x, acc.z);
            acc.w = fmaf(w, v1.y, acc.w);
        }
        __half2* o = reinterpret_cast<__half2*>(outH + (size_t)a * outStrideH + tx * 4);
        o[0] = __floats2half2_rn(acc.x, acc.y);
        o[1] = __floats2half2_rn(acc.z, acc.w);
    }
}

// ---------------- readout (float4, ah fp32) ----------------
__global__ __launch_bounds__(320) void readout4(
    const float4* __restrict__ ah4, const float* __restrict__ w_atoms,
    const float* __restrict__ dop, float4* __restrict__ out4)
{
    const int tx = threadIdx.x;
    const int ty = threadIdx.y;
    const int m  = blockIdx.x * 4 + ty;
    if (m >= N_MOLS || tx >= H4) return;
    const int base = 1 + m * ATOMS_PER_MOL;
    float4 s = make_float4(0.f, 0.f, 0.f, 0.f);
    float ws = 0.f;
    #pragma unroll 5
    for (int i = 0; i < ATOMS_PER_MOL; i++) {
        float  w = w_atoms[base + i];
        float4 v = ah4[(size_t)(base + i) * H4 + tx];
        ws += w;
        s.x = fmaf(w, v.x, s.x);
        s.y = fmaf(w, v.y, s.y);
        s.z = fmaf(w, v.z, s.z);
        s.w = fmaf(w, v.w, s.w);
    }
    float sc = dop[m] / ws;
    s.x *= sc; s.y *= sc; s.z *= sc; s.w *= sc;
    out4[(size_t)m * H4 + tx] = s;
}

// ---------------- launch ----------------
extern "C" void kernel_launch(void* const* d_in, const int* in_sizes, int n_in,
                              void* d_out, int out_size)
{
    const float* f_atoms = (const float*)d_in[0];
    const float* f_bonds = (const float*)d_in[1];
    const float* w_atoms = (const float*)d_in[2];
    const float* w_bonds = (const float*)d_in[3];
    const float* dop     = (const float*)d_in[4];
    const float* W_i     = (const float*)d_in[5];
    const float* W_h     = (const float*)d_in[6];
    const float* W_o     = (const float*)d_in[7];
    const float* b_o     = (const float*)d_in[8];
    const int*   a2b     = (const int*)d_in[9];
    const int*   b2a     = (const int*)d_in[10];
    const int*   b2revb  = (const int*)d_in[11];
    float* out = (float*)d_out;

    float *ah;
    __half *inpH, *msgA, *msgB, *amsgH, *fbtH, *catH, *WiT, *WhT, *WoT;
    cudaGetSymbolAddress((void**)&ah,    g_ah);
    cudaGetSymbolAddress((void**)&inpH,  g_inpH);
    cudaGetSymbolAddress((void**)&msgA,  g_msgA);
    cudaGetSymbolAddress((void**)&msgB,  g_msgB);
    cudaGetSymbolAddress((void**)&amsgH, g_amsgH);
    cudaGetSymbolAddress((void**)&fbtH,  g_fbtH);
    cudaGetSymbolAddress((void**)&catH,  g_catH);
    cudaGetSymbolAddress((void**)&WiT,   g_WiT);
    cudaGetSymbolAddress((void**)&WhT,   g_WhT);
    cudaGetSymbolAddress((void**)&WoT,   g_WoT);

    cudaFuncSetAttribute(hgemm300<0>, cudaFuncAttributeMaxDynamicSharedMemorySize, SMEM_PLAIN);
    cudaFuncSetAttribute(hgemm300<1>, cudaFuncAttributeMaxDynamicSharedMemorySize, SMEM_FUSED);

    dim3 blk(256);
    dim3 gridBonds(2, (N_BONDS + TBM - 1) / TBM);   // (2, 1563)
    dim3 gridAtoms(2, (N_ATOMS + TBM - 1) / TBM);   // (2, 782)
    dim3 vblk(80, 4);

    {
        int n;
        n = N_BONDS * FBH;
        cvt_padH      <<<(n + 255) / 256, 256>>>(f_bonds, fbtH, n, BOND_FDIM, FBH);
        n = N_ATOMS * 140;
        cvt_cat_atomsH<<<(n + 255) / 256, 256>>>(f_atoms, catH, n);
        n = HIDDEN * 160;
        cvt_wtrH      <<<(n + 255) / 256, 256>>>(W_i, WiT, BOND_FDIM, 160, n);
        n = HIDDEN * MSGH;
        cvt_wtrH      <<<(n + 255) / 256, 256>>>(W_h, WhT, HIDDEN, MSGH, n);
        n = HIDDEN * CATH;
        cvt_wo_trH    <<<(n + 255) / 256, 256>>>(W_o, WoT, n);
    }

    // inpH(fp16) = f_bonds @ W_i (pre-relu) ; msgA(fp16) = relu(...)   nCh = 5
    hgemm300<0><<<gridBonds, blk, SMEM_PLAIN>>>(fbtH, FBH, WiT, 160,
                                                msgA, MSGH, nullptr,
                                                nullptr, 0, nullptr,
                                                inpH, MSGH, N_BONDS, 5, 1,
                                                nullptr, nullptr, nullptr, nullptr, nullptr);

    __half* cur = msgA;
    __half* nxt = msgB;
    for (int d = 0; d < DEPTH - 1; ++d) {
        gather_atomsH<<<(N_ATOMS + 3) / 4, vblk>>>(cur, w_bonds, a2b, amsgH, MSGH);
        // nxt = relu(inpH + (amsg[b2a] - w*cur[b2revb]) @ W_h)  -- bond_update fused, nCh = 10
        hgemm300<1><<<gridBonds, blk, SMEM_FUSED>>>(nullptr, MSGH, WhT, MSGH,
                                                    nxt, MSGH, nullptr,
                                                    inpH, MSGH, nullptr,
                                                    nullptr, 0, N_BONDS, 10, 1,
                                                    amsgH, cur, b2a, b2revb, w_bonds);
        __half* sw = cur; cur = nxt; nxt = sw;
    }

    // final gather writes fp16 amsg straight into cat cols [0,300)
    gather_atomsH<<<(N_ATOMS + 3) / 4, vblk>>>(cur, w_bonds, a2b, catH, CATH);

    // ah(fp32) = relu([amsg | f_atoms] @ WoC + b_o)                     nCh = 14
    hgemm300<0><<<gridAtoms, blk, SMEM_PLAIN>>>(catH, CATH, WoT, CATH,
                                                nullptr, 0, ah,
                                                nullptr, 0, b_o,
                                                nullptr, 0, N_ATOMS, 14, 1,
                                                nullptr, nullptr, nullptr, nullptr, nullptr);

    readout4<<<(N_MOLS + 3) / 4, vblk>>>(
        (const float4*)ah, w_atoms, dop, (float4*)out);
}

// round 17
// speedup vs baseline: 1.2799x; 1.2799x over previous
#include <cuda_runtime.h>
#include <cuda_fp16.h>
#include <cstdint>

#define N_MOLS        2000
#define ATOMS_PER_MOL 50
#define N_ATOMS       (N_MOLS * ATOMS_PER_MOL + 1)   // 100001
#define N_BONDS       200001
#define MAX_NB        6
#define ATOM_FDIM     133
#define BOND_FDIM     147
#define HIDDEN        300
#define DEPTH         4
#define H4            (HIDDEN / 4)
#define FBH           152                    // f_bonds halves padded (304B rows)
#define MSGH          304                    // msg/amsg/tmp row stride in halves (608B = 38*16)
#define CATH          440                    // cat K padded halves (880B = 55*16)

// ---------------- persistent scratch (zero-initialized; pads stay 0) ----------------
__device__ __align__(16) float  g_inp [(size_t)N_BONDS * HIDDEN];   // fp32 (precision anchor)
__device__ __align__(16) float  g_ah  [(size_t)N_ATOMS * HIDDEN];   // fp32
__device__ __align__(16) __half g_msgH [(size_t)N_BONDS * MSGH];    // fp16 message
__device__ __align__(16) __half g_amsgH[(size_t)N_ATOMS * MSGH];    // fp16 atom aggregate
__device__ __align__(16) __half g_tmpH [(size_t)N_BONDS * MSGH];    // fp16 bond message (GEMM A)
__device__ __align__(16) __half g_fbtH [(size_t)N_BONDS * FBH];     // fp16 f_bonds, padded
__device__ __align__(16) __half g_catH [(size_t)N_ATOMS * CATH];    // fp16 [amsg | f_atoms | 0]
__device__ __align__(16) __half g_WiT  [HIDDEN * 160];              // W_i^T  [300][160]
__device__ __align__(16) __half g_WhT  [HIDDEN * MSGH];             // W_h^T  [300][304]
__device__ __align__(16) __half g_WoT  [HIDDEN * CATH];             // WoC^T  [300][440]

// ---------------- pre-conversion kernels ----------------
__global__ void cvt_padH(const float* __restrict__ in, __half* __restrict__ out,
                         int n, int cin, int coutH) {
    int i = blockIdx.x * blockDim.x + threadIdx.x;
    if (i >= n) return;
    int r = i / coutH, c = i - r * coutH;
    out[i] = (c < cin) ? __float2half_rn(in[(size_t)r * cin + c]) : __half(0.f);
}
__global__ void cvt_wtrH(const float* __restrict__ W, __half* __restrict__ Bt,
                         int K, int kpad, int n) {   // n = 300*kpad
    int i = blockIdx.x * blockDim.x + threadIdx.x;
    if (i >= n) return;
    int nn = i / kpad, k = i - nn * kpad;
    Bt[i] = (k < K) ? __float2half_rn(W[(size_t)k * HIDDEN + nn]) : __half(0.f);
}
__global__ void cvt_wo_trH(const float* __restrict__ Wo, __half* __restrict__ Bt, int n) {
    int i = blockIdx.x * blockDim.x + threadIdx.x;   // n = 300*CATH
    if (i >= n) return;
    int nn = i / CATH, kp = i - nn * CATH;
    float v = 0.f;
    if (kp < HIDDEN)                  v = Wo[(size_t)(ATOM_FDIM + kp) * HIDDEN + nn];
    else if (kp < HIDDEN + ATOM_FDIM) v = Wo[(size_t)(kp - HIDDEN) * HIDDEN + nn];
    Bt[i] = __float2half_rn(v);
}
__global__ void cvt_cat_atomsH(const float* __restrict__ fa, __half* __restrict__ cat, int n) {
    int i = blockIdx.x * blockDim.x + threadIdx.x;   // n = N_ATOMS * 140
    if (i >= n) return;
    int r = i / 140, c = i - r * 140;
    cat[(size_t)r * CATH + HIDDEN + c] =
        (c < ATOM_FDIM) ? __float2half_rn(fa[(size_t)r * ATOM_FDIM + c]) : __half(0.f);
}

// ---------------- fp16 mma ----------------
__device__ __forceinline__ void mma_f16(float* c, const uint32_t* a, const uint32_t* b) {
    asm volatile(
        "mma.sync.aligned.m16n8k16.row.col.f32.f16.f16.f32 "
        "{%0,%1,%2,%3}, {%4,%5,%6,%7}, {%8,%9}, {%0,%1,%2,%3};"
        : "+f"(c[0]), "+f"(c[1]), "+f"(c[2]), "+f"(c[3])
        : "r"(a[0]), "r"(a[1]), "r"(a[2]), "r"(a[3]), "r"(b[0]), "r"(b[1]));
}

// ---------------- pipelined fp16 tensor-core GEMM, 64x40 warp tiles, TBK=32 (R13) ----------------
#define TBM 128
#define TBN 160
#define STAGES 4
#define RST 20
#define A_WORDS (TBM * RST)            // 2560
#define B_WORDS (TBN * RST)            // 3200
#define SMEM_BYTES (STAGES * (A_WORDS + B_WORDS) * 4)   // 92160

__global__ __launch_bounds__(256, 2) void hgemm300(
    const __half* __restrict__ A, int ldaH,
    const __half* __restrict__ Bt, int ldbH,
    __half* __restrict__ Ch, int ldcH,
    float* __restrict__ Cf,
    const float* __restrict__ addsrc,
    const float* __restrict__ bias,
    float* __restrict__ rawoutF,
    int M, int nCh, int doRelu)
{
    extern __shared__ uint32_t sm[];
    uint32_t* sA = sm;
    uint32_t* sB = sm + STAGES * A_WORDS;
    const uint32_t sAaddr = (uint32_t)__cvta_generic_to_shared(sA);
    const uint32_t sBaddr = (uint32_t)__cvta_generic_to_shared(sB);

    const int tid  = threadIdx.x;
    const int lane = tid & 31;
    const int warp = tid >> 5;
    const int g = lane >> 2;
    const int t = lane & 3;
    const int m0w = (warp & 1) * 64;
    const int n0w = (warp >> 1) * 40;

    const int rowBase = blockIdx.y * TBM;
    const int colBase = blockIdx.x * TBN;

    auto issue = [&](int c) {
        const int stg = c % STAGES;
        #pragma unroll
        for (int it = 0; it < 2; it++) {
            int e   = it * 256 + tid;
            int row = e >> 2;
            int k16 = e & 3;
            int gr  = rowBase + row;
            int k0h = c * 32 + k16 * 8;
            int by  = (gr < M && k0h < ldaH) ? 16 : 0;
            const __half* src = by ? (A + (size_t)gr * ldaH + k0h) : A;
            uint32_t dst = sAaddr + (uint32_t)(stg * A_WORDS + row * RST + k16 * 4) * 4u;
            asm volatile("cp.async.ca.shared.global [%0], [%1], 16, %2;"
                         :: "r"(dst), "l"(src), "r"(by) : "memory");
        }
        #pragma unroll
        for (int it = 0; it < 3; it++) {
            int e = it * 256 + tid;
            if (it == 2 && tid >= 128) break;
            int n   = e >> 2;
            int k16 = e & 3;
            int gn  = colBase + n;
            int k0h = c * 32 + k16 * 8;
            int by  = (gn < HIDDEN && k0h < ldbH) ? 16 : 0;
            const __half* src = by ? (Bt + (size_t)gn * ldbH + k0h) : Bt;
            uint32_t dst = sBaddr + (uint32_t)(stg * B_WORDS + n * RST + k16 * 4) * 4u;
            asm volatile("cp.async.ca.shared.global [%0], [%1], 16, %2;"
                         :: "r"(dst), "l"(src), "r"(by) : "memory");
        }
    };

    float acc[4][5][4];
    #pragma unroll
    for (int i = 0; i < 4; i++)
        #pragma unroll
        for (int j = 0; j < 5; j++)
            #pragma unroll
            for (int q = 0; q < 4; q++) acc[i][j][q] = 0.f;

    #pragma unroll
    for (int s = 0; s < STAGES - 1; s++) {
        if (s < nCh) issue(s);
        asm volatile("cp.async.commit_group;" ::: "memory");
    }

    for (int c = 0; c < nCh; c++) {
        asm volatile("cp.async.wait_group %0;" :: "n"(STAGES - 2) : "memory");
        __syncthreads();
        const uint32_t* As = sA + (c % STAGES) * A_WORDS;
        const uint32_t* Bs = sB + (c % STAGES) * B_WORDS;

        #pragma unroll
        for (int ks = 0; ks < 2; ks++) {
            const int kkw = ks * 8;
            uint32_t af[4][4];
            #pragma unroll
            for (int mt = 0; mt < 4; mt++) {
                int r = m0w + mt * 16;
                af[mt][0] = As[(r + g    ) * RST + kkw + t    ];
                af[mt][1] = As[(r + g + 8) * RST + kkw + t    ];
                af[mt][2] = As[(r + g    ) * RST + kkw + t + 4];
                af[mt][3] = As[(r + g + 8) * RST + kkw + t + 4];
            }
            uint32_t bf[5][2];
            #pragma unroll
            for (int nt = 0; nt < 5; nt++) {
                int nc = n0w + nt * 8 + g;
                bf[nt][0] = Bs[nc * RST + kkw + t    ];
                bf[nt][1] = Bs[nc * RST + kkw + t + 4];
            }
            #pragma unroll
            for (int mt = 0; mt < 4; mt++)
                #pragma unroll
                for (int nt = 0; nt < 5; nt++)
                    mma_f16(acc[mt][nt], af[mt], bf[nt]);
        }
        int nx = c + STAGES - 1;
        if (nx < nCh) issue(nx);
        asm volatile("cp.async.commit_group;" ::: "memory");
    }

    // epilogue (col pairs are even and never straddle the N=300 edge)
    #pragma unroll
    for (int mt = 0; mt < 4; mt++) {
        #pragma unroll
        for (int half = 0; half < 2; half++) {
            int row = rowBase + m0w + mt * 16 + g + half * 8;
            if (row >= M) continue;
            #pragma unroll
            for (int nt = 0; nt < 5; nt++) {
                int col = colBase + n0w + nt * 8 + t * 2;
                if (col >= HIDDEN) continue;
                float vx = acc[mt][nt][half * 2 + 0];
                float vy = acc[mt][nt][half * 2 + 1];
                if (bias)   { vx += bias[col]; vy += bias[col + 1]; }
                if (addsrc) {
                    float2 a = *reinterpret_cast<const float2*>(addsrc + (size_t)row * HIDDEN + col);
                    vx += a.x; vy += a.y;
                }
                if (rawoutF) {
                    float2 r; r.x = vx; r.y = vy;
                    *reinterpret_cast<float2*>(rawoutF + (size_t)row * HIDDEN + col) = r;
                }
                if (doRelu) { vx = fmaxf(vx, 0.f); vy = fmaxf(vy, 0.f); }
                if (Ch) {
                    *reinterpret_cast<__half2*>(Ch + (size_t)row * ldcH + col) =
                        __floats2half2_rn(vx, vy);
                } else {
                    float2 o; o.x = vx; o.y = vy;
                    *reinterpret_cast<float2*>(Cf + (size_t)row * HIDDEN + col) = o;
                }
            }
        }
    }
}

// ---------------- helpers: uint4 <-> 8 fp32 ----------------
__device__ __forceinline__ void h8_to_f8(uint4 v, float* f) {
    const __half2* h = reinterpret_cast<const __half2*>(&v);
    float2 a = __half22float2(h[0]), b = __half22float2(h[1]);
    float2 c = __half22float2(h[2]), d = __half22float2(h[3]);
    f[0]=a.x; f[1]=a.y; f[2]=b.x; f[3]=b.y; f[4]=c.x; f[5]=c.y; f[6]=d.x; f[7]=d.y;
}
__device__ __forceinline__ uint4 f8_to_h8(const float* f) {
    uint4 v;
    __half2* h = reinterpret_cast<__half2*>(&v);
    h[0] = __floats2half2_rn(f[0], f[1]);
    h[1] = __floats2half2_rn(f[2], f[3]);
    h[2] = __floats2half2_rn(f[4], f[5]);
    h[3] = __floats2half2_rn(f[6], f[7]);
    return v;
}

// ---------------- atom aggregation, 16B lanes: (38,8) block, 8 atoms/block ----------------
// TOCAT=0: out stride MSGH, full 38-chunk store (pads become 0).
// TOCAT=1: out stride CATH; chunk 37 covers halves [296,304) but cat col 300 starts
//          f_atoms -> store only the first 8B of chunk 37.
template <int TOCAT>
__global__ __launch_bounds__(304) void gather16(
    const __half* __restrict__ msgH, const float* __restrict__ w_bonds,
    const int* __restrict__ a2b, __half* __restrict__ outH)
{
    const int tx = threadIdx.x;        // 0..37
    const int ty = threadIdx.y;        // 0..7
    const int a  = blockIdx.x * 8 + ty;
    __shared__ int   sb[8][MAX_NB];
    __shared__ float sw[8][MAX_NB];
    if (a < N_ATOMS && tx < MAX_NB) {
        int b = a2b[(size_t)a * MAX_NB + tx];
        sb[ty][tx] = b;
        sw[ty][tx] = w_bonds[b];
    }
    __syncthreads();
    if (a >= N_ATOMS) return;

    float acc[8];
    #pragma unroll
    for (int i = 0; i < 8; i++) acc[i] = 0.f;

    #pragma unroll
    for (int k = 0; k < MAX_NB; k++) {
        float w = sw[ty][k];
        uint4 v = *reinterpret_cast<const uint4*>(
            msgH + (size_t)sb[ty][k] * MSGH + tx * 8);
        float f[8]; h8_to_f8(v, f);
        #pragma unroll
        for (int i = 0; i < 8; i++) acc[i] = fmaf(w, f[i], acc[i]);
    }
    uint4 o = f8_to_h8(acc);
    const int strideH = TOCAT ? CATH : MSGH;
    __half* dst = outH + (size_t)a * strideH + tx * 8;
    if (TOCAT && tx == 37) {
        // only halves [296,300): first 8B of the chunk
        *reinterpret_cast<uint2*>(dst) = make_uint2(o.x, o.y);
    } else {
        *reinterpret_cast<uint4*>(dst) = o;
    }
}

// ---------------- bond update, 16B lanes: (38,8) block, 8 bonds/block ----------------
__global__ __launch_bounds__(304) void bond16(
    const __half* __restrict__ amsgH, const __half* __restrict__ msgH,
    const float* __restrict__ w_bonds,
    const int* __restrict__ b2a, const int* __restrict__ b2revb,
    __half* __restrict__ tmpH)
{
    const int tx = threadIdx.x;        // 0..37
    const int ty = threadIdx.y;        // 0..7
    const int b  = blockIdx.x * 8 + ty;
    __shared__ int   sa[8], srb[8];
    __shared__ float sw[8];
    if (b < N_BONDS && tx == 0) { sa[ty] = b2a[b]; srb[ty] = b2revb[b]; sw[ty] = w_bonds[b]; }
    __syncthreads();
    if (b >= N_BONDS) return;

    uint4 va = *reinterpret_cast<const uint4*>(amsgH + (size_t)sa[ty]  * MSGH + tx * 8);
    uint4 vm = *reinterpret_cast<const uint4*>(msgH  + (size_t)srb[ty] * MSGH + tx * 8);
    float fa[8], fm[8], fo[8];
    h8_to_f8(va, fa); h8_to_f8(vm, fm);
    float w = sw[ty];
    #pragma unroll
    for (int i = 0; i < 8; i++) fo[i] = fa[i] - w * fm[i];
    *reinterpret_cast<uint4*>(tmpH + (size_t)b * MSGH + tx * 8) = f8_to_h8(fo);
    // pads: inputs zero -> outputs zero; no special-case needed
}

// ---------------- readout (float4, ah fp32) ----------------
__global__ __launch_bounds__(320) void readout4(
    const float4* __restrict__ ah4, const float* __restrict__ w_atoms,
    const float* __restrict__ dop, float4* __restrict__ out4)
{
    const int tx = threadIdx.x;
    const int ty = threadIdx.y;
    const int m  = blockIdx.x * 4 + ty;
    if (m >= N_MOLS || tx >= H4) return;
    const int base = 1 + m * ATOMS_PER_MOL;
    float4 s = make_float4(0.f, 0.f, 0.f, 0.f);
    float ws = 0.f;
    #pragma unroll 5
    for (int i = 0; i < ATOMS_PER_MOL; i++) {
        float  w = w_atoms[base + i];
        float4 v = ah4[(size_t)(base + i) * H4 + tx];
        ws += w;
        s.x = fmaf(w, v.x, s.x);
        s.y = fmaf(w, v.y, s.y);
        s.z = fmaf(w, v.z, s.z);
        s.w = fmaf(w, v.w, s.w);
    }
    float sc = dop[m] / ws;
    s.x *= sc; s.y *= sc; s.z *= sc; s.w *= sc;
    out4[(size_t)m * H4 + tx] = s;
}

// ---------------- launch ----------------
extern "C" void kernel_launch(void* const* d_in, const int* in_sizes, int n_in,
                              void* d_out, int out_size)
{
    const float* f_atoms = (const float*)d_in[0];
    const float* f_bonds = (const float*)d_in[1];
    const float* w_atoms = (const float*)d_in[2];
    const float* w_bonds = (const float*)d_in[3];
    const float* dop     = (const float*)d_in[4];
    const float* W_i     = (const float*)d_in[5];
    const float* W_h     = (const float*)d_in[6];
    const float* W_o     = (const float*)d_in[7];
    const float* b_o     = (const float*)d_in[8];
    const int*   a2b     = (const int*)d_in[9];
    const int*   b2a     = (const int*)d_in[10];
    const int*   b2revb  = (const int*)d_in[11];
    float* out = (float*)d_out;

    float *inp, *ah;
    __half *msgH, *amsgH, *tmpH, *fbtH, *catH, *WiT, *WhT, *WoT;
    cudaGetSymbolAddress((void**)&inp,   g_inp);
    cudaGetSymbolAddress((void**)&ah,    g_ah);
    cudaGetSymbolAddress((void**)&msgH,  g_msgH);
    cudaGetSymbolAddress((void**)&amsgH, g_amsgH);
    cudaGetSymbolAddress((void**)&tmpH,  g_tmpH);
    cudaGetSymbolAddress((void**)&fbtH,  g_fbtH);
    cudaGetSymbolAddress((void**)&catH,  g_catH);
    cudaGetSymbolAddress((void**)&WiT,   g_WiT);
    cudaGetSymbolAddress((void**)&WhT,   g_WhT);
    cudaGetSymbolAddress((void**)&WoT,   g_WoT);

    cudaFuncSetAttribute(hgemm300, cudaFuncAttributeMaxDynamicSharedMemorySize, SMEM_BYTES);

    dim3 blk(256);
    dim3 gridBonds(2, (N_BONDS + TBM - 1) / TBM);   // (2, 1563)
    dim3 gridAtoms(2, (N_ATOMS + TBM - 1) / TBM);   // (2, 782)
    dim3 vblk16(38, 8);

    {
        int n;
        n = N_BONDS * FBH;
        cvt_padH      <<<(n + 255) / 256, 256>>>(f_bonds, fbtH, n, BOND_FDIM, FBH);
        n = N_ATOMS * 140;
        cvt_cat_atomsH<<<(n + 255) / 256, 256>>>(f_atoms, catH, n);
        n = HIDDEN * 160;
        cvt_wtrH      <<<(n + 255) / 256, 256>>>(W_i, WiT, BOND_FDIM, 160, n);
        n = HIDDEN * MSGH;
        cvt_wtrH      <<<(n + 255) / 256, 256>>>(W_h, WhT, HIDDEN, MSGH, n);
        n = HIDDEN * CATH;
        cvt_wo_trH    <<<(n + 255) / 256, 256>>>(W_o, WoT, n);
    }

    // inp(fp32) = f_bonds @ W_i (pre-relu) ; msgH(fp16) = relu(...)   nCh = 5
    hgemm300<<<gridBonds, blk, SMEM_BYTES>>>(fbtH, FBH, WiT, 160,
                                             msgH, MSGH, nullptr,
                                             nullptr, nullptr, inp, N_BONDS, 5, 1);

    for (int d = 0; d < DEPTH - 1; ++d) {
        gather16<0><<<(N_ATOMS + 7) / 8, vblk16>>>(msgH, w_bonds, a2b, amsgH);
        bond16     <<<(N_BONDS + 7) / 8, vblk16>>>(amsgH, msgH, w_bonds, b2a, b2revb, tmpH);
        // msgH = relu(inp + tmp @ W_h)                                 nCh = 10
        hgemm300<<<gridBonds, blk, SMEM_BYTES>>>(tmpH, MSGH, WhT, MSGH,
                                                 msgH, MSGH, nullptr,
                                                 inp, nullptr, nullptr, N_BONDS, 10, 1);
    }

    // final gather writes fp16 amsg straight into cat cols [0,300)
    gather16<1><<<(N_ATOMS + 7) / 8, vblk16>>>(msgH, w_bonds, a2b, catH);

    // ah(fp32) = relu([amsg | f_atoms] @ WoC + b_o)                    nCh = 14
    hgemm300<<<gridAtoms, blk, SMEM_BYTES>>>(catH, CATH, WoT, CATH,
                                             nullptr, 0, ah,
                                             nullptr, b_o, nullptr, N_ATOMS, 14, 1);

    readout4<<<(N_MOLS + 3) / 4, 
               dim3(80, 4)>>>((const float4*)ah, w_atoms, dop, (float4*)out);
}